// round 1
// baseline (speedup 1.0000x reference)
#include <cuda_runtime.h>
#include <cstdint>

// Problem constants
#define BATCH   512
#define DIMC    64
#define BOOK    1024
#define EMB     64
#define CWDIM   (DIMC * EMB)            // 4096

// Output layout (floats): cw | one_hot | new_codebook | new_ema
#define CW_OFF    0
#define CW_SIZE   (BATCH * CWDIM)                    // 2,097,152
#define OH_OFF    (CW_OFF + CW_SIZE)                 // 2,097,152
#define OH_SIZE   (BATCH * DIMC * BOOK)              // 33,554,432
#define NCB_OFF   (OH_OFF + OH_SIZE)                 // 35,651,584
#define NCB_SIZE  (DIMC * BOOK * EMB)                // 4,194,304
#define NEMA_OFF  (NCB_OFF + NCB_SIZE)               // 39,845,888
#define NEMA_SIZE (DIMC * BOOK)                      // 65,536

__device__ int g_idx[BATCH * DIMC];

static __device__ __forceinline__ unsigned long long pack2(float v) {
    unsigned long long r;
    asm("mov.b64 %0, {%1, %1};" : "=l"(r) : "r"(__float_as_uint(v)));
    return r;
}

// ---------------------------------------------------------------------------
// Kernel 1: fused (a) zero one_hot, (b) init new_codebook = DECAY*cb and
// new_ema = DECAY*ema, (c) batched distance-argmin via f32x2 packed FMA.
//
// Grid: (4, 64) — blockIdx.x = 128-row tile of B, blockIdx.y = d.
// 256 threads. Dynamic smem:
//   xs[e][row]  : 64 x 130 floats (transposed x tile, padded, row pairs 8B)
//   cs[k][e]    : 64 x 65 floats  (codebook k-tile, padded -> conflict-free)
//   bsq[64]
// Thread (tr,tc)=(t>>4,t&15): rows = pairs p=tr+16i (i<4) -> 8 rows;
// ks = tc+16j (j<4) per 64-wide k tile. acc is f32x2 over the row pair.
// ---------------------------------------------------------------------------
extern __shared__ float sm_dyn[];

__global__ void __launch_bounds__(256, 2)
argmin_kernel(const float* __restrict__ x, const float* __restrict__ cb,
              const float* __restrict__ ema, float* __restrict__ out)
{
    const float DECAYF = 0.999f;
    float* xs  = sm_dyn;              // 64*130
    float* cs  = sm_dyn + 64 * 130;   // 64*65
    float* bsq = cs + 64 * 65;        // 64

    const int t  = threadIdx.x;
    const int d  = blockIdx.y;
    const int b0 = blockIdx.x * 128;
    const int blk = d * 4 + blockIdx.x;   // 0..255

    // ---- fused output prep (fire-and-forget stores, hidden under compute) ----
    {
        float4 z = make_float4(0.f, 0.f, 0.f, 0.f);
        float4* oh4 = (float4*)(out + OH_OFF);
        size_t base = (size_t)blk * (OH_SIZE / 256 / 4);   // 32768 float4 per block
        #pragma unroll 4
        for (int it = 0; it < 128; ++it)
            oh4[base + t + it * 256] = z;

        const float4* cb4  = (const float4*)cb;
        float4*       ncb4 = (float4*)(out + NCB_OFF);
        size_t cbase = (size_t)blk * (NCB_SIZE / 256 / 4); // 4096 float4 per block
        #pragma unroll 4
        for (int it = 0; it < 16; ++it) {
            float4 v = cb4[cbase + t + it * 256];
            v.x *= DECAYF; v.y *= DECAYF; v.z *= DECAYF; v.w *= DECAYF;
            ncb4[cbase + t + it * 256] = v;
        }
        if (t < 64) {
            const float4* em4 = (const float4*)ema;
            float4*       ne4 = (float4*)(out + NEMA_OFF);
            size_t eb = (size_t)blk * 64 + t;              // 16384 float4 total
            float4 v = em4[eb];
            v.x *= DECAYF; v.y *= DECAYF; v.z *= DECAYF; v.w *= DECAYF;
            ne4[eb] = v;
        }
    }

    // ---- load x tile, transposed into xs[e][row] ----
    #pragma unroll
    for (int it = 0; it < 8; ++it) {
        int idx = t + it * 256;       // 0..2047
        int row = idx >> 4;           // 0..127
        int e4  = (idx & 15) * 4;
        float4 v = *(const float4*)(x + (size_t)(b0 + row) * CWDIM + d * EMB + e4);
        xs[(e4 + 0) * 130 + row] = v.x;
        xs[(e4 + 1) * 130 + row] = v.y;
        xs[(e4 + 2) * 130 + row] = v.z;
        xs[(e4 + 3) * 130 + row] = v.w;
    }

    const int tr = t >> 4, tc = t & 15;
    float bestS[8];
    int   bestI[8];
    #pragma unroll
    for (int m = 0; m < 8; ++m) { bestS[m] = 3.4e38f; bestI[m] = 0; }

    const float* cbd = cb + (size_t)d * (BOOK * EMB);

    for (int kt = 0; kt < 16; ++kt) {
        __syncthreads();   // protect cs/bsq from previous tile's readers
        // load 64 x 64 codebook k-tile into cs[k][e] (pad 65)
        #pragma unroll
        for (int it = 0; it < 4; ++it) {
            int idx = t + it * 256;   // 0..1023
            int kk  = idx >> 4;       // 0..63
            int e4  = (idx & 15) * 4;
            float4 v = *(const float4*)(cbd + (size_t)(kt * 64 + kk) * EMB + e4);
            cs[kk * 65 + e4 + 0] = v.x;
            cs[kk * 65 + e4 + 1] = v.y;
            cs[kk * 65 + e4 + 2] = v.z;
            cs[kk * 65 + e4 + 3] = v.w;
        }
        __syncthreads();
        if (t < 64) {
            float s = 0.f;
            #pragma unroll
            for (int e = 0; e < EMB; ++e) { float c = cs[t * 65 + e]; s = fmaf(c, c, s); }
            bsq[t] = s;
        }
        __syncthreads();

        unsigned long long acc[4][4];
        #pragma unroll
        for (int i = 0; i < 4; ++i)
            #pragma unroll
            for (int j = 0; j < 4; ++j) acc[i][j] = 0ull;

        #pragma unroll 4
        for (int e = 0; e < EMB; ++e) {
            unsigned long long a2[4];
            #pragma unroll
            for (int i = 0; i < 4; ++i)
                a2[i] = *(const unsigned long long*)(xs + e * 130 + 2 * (tr + 16 * i));
            #pragma unroll
            for (int j = 0; j < 4; ++j) {
                unsigned long long bb = pack2(cs[(tc + 16 * j) * 65 + e]);
                #pragma unroll
                for (int i = 0; i < 4; ++i)
                    asm("fma.rn.f32x2 %0, %1, %2, %0;"
                        : "+l"(acc[i][j]) : "l"(a2[i]), "l"(bb));
            }
        }

        // epilogue: score = bsq[k] - 2*dot  (x_sq omitted: constant per row)
        #pragma unroll
        for (int j = 0; j < 4; ++j) {
            int kk = tc + 16 * j;
            int k  = kt * 64 + kk;
            float bq = bsq[kk];
            #pragma unroll
            for (int i = 0; i < 4; ++i) {
                unsigned int ulo, uhi;
                asm("mov.b64 {%0, %1}, %2;" : "=r"(ulo), "=r"(uhi) : "l"(acc[i][j]));
                float s0 = fmaf(-2.f, __uint_as_float(ulo), bq);
                float s1 = fmaf(-2.f, __uint_as_float(uhi), bq);
                if (s0 < bestS[2 * i])     { bestS[2 * i]     = s0; bestI[2 * i]     = k; }
                if (s1 < bestS[2 * i + 1]) { bestS[2 * i + 1] = s1; bestI[2 * i + 1] = k; }
            }
        }
    }

    // reduce across the 16 tc threads (half-warp), ties -> lowest index
    #pragma unroll
    for (int m = 0; m < 8; ++m) {
        float s  = bestS[m];
        int   ki = bestI[m];
        #pragma unroll
        for (int off = 8; off > 0; off >>= 1) {
            float os = __shfl_down_sync(0xffffffffu, s,  off, 16);
            int   oi = __shfl_down_sync(0xffffffffu, ki, off, 16);
            if (os < s || (os == s && oi < ki)) { s = os; ki = oi; }
        }
        if (tc == 0) {
            int row = 2 * (tr + 16 * (m >> 1)) + (m & 1);
            g_idx[(b0 + row) * DIMC + d] = ki;
        }
    }
}

// ---------------------------------------------------------------------------
// Kernel 2: gather cw, set one_hot ones, EMA scatter-adds.
// One warp per (b,d); lane handles 2 embedding elements.
// ---------------------------------------------------------------------------
__global__ void __launch_bounds__(256)
scatter_kernel(const float* __restrict__ x, const float* __restrict__ cb,
               const float* __restrict__ ema, float* __restrict__ out)
{
    const float GAINF = (float)(1.0 - 0.999);
    const float EPSF  = 1e-6f;
    float* cw   = out + CW_OFF;
    float* oh   = out + OH_OFF;
    float* ncb  = out + NCB_OFF;
    float* nema = out + NEMA_OFF;

    int b    = blockIdx.x;
    int warp = threadIdx.x >> 5;
    int lane = threadIdx.x & 31;

    #pragma unroll
    for (int dd = 0; dd < 8; ++dd) {
        int d = warp * 8 + dd;
        int k = g_idx[b * DIMC + d];
        float g = GAINF / (ema[d * BOOK + k] + EPSF);

        size_t co = ((size_t)d * BOOK + k) * EMB + 2 * lane;
        size_t xo = (size_t)b * CWDIM + d * EMB + 2 * lane;
        float2 c2 = *(const float2*)(cb + co);
        float2 x2 = *(const float2*)(x + xo);

        // cw = x + (c - x): mirror reference fp order exactly
        float2 w;
        w.x = x2.x + (c2.x - x2.x);
        w.y = x2.y + (c2.y - x2.y);
        *(float2*)(cw + xo) = w;

        atomicAdd(ncb + co,     g * x2.x);
        atomicAdd(ncb + co + 1, g * x2.y);

        if (lane == 0) {
            oh[(size_t)b * (DIMC * BOOK) + (size_t)d * BOOK + k] = 1.0f;
            atomicAdd(nema + d * BOOK + k, GAINF);
        }
    }
}

// ---------------------------------------------------------------------------
extern "C" void kernel_launch(void* const* d_in, const int* in_sizes, int n_in,
                              void* d_out, int out_size)
{
    const float* x   = (const float*)d_in[0];
    const float* cb  = (const float*)d_in[1];
    const float* ema = (const float*)d_in[2];
    float* out = (float*)d_out;

    const int smem = (64 * 130 + 64 * 65 + 64) * (int)sizeof(float);  // 50432 B
    cudaFuncSetAttribute(argmin_kernel,
                         cudaFuncAttributeMaxDynamicSharedMemorySize, smem);

    dim3 grid(4, 64);
    argmin_kernel<<<grid, 256, smem>>>(x, cb, ema, out);
    scatter_kernel<<<BATCH, 256>>>(x, cb, ema, out);
}